// round 7
// baseline (speedup 1.0000x reference)
#include <cuda_runtime.h>
#include <cuda_bf16.h>
#include <cstdint>

#define N_MAX 100000
#define E_MAX 1000000
#define F 64
#define ALPHA 0.2f

// Scratch (static __device__ allocation — no cudaMalloc allowed)
__device__ float  g_Wh[N_MAX * F];      // 25.6 MB (L2-resident)
__device__ float  g_ssrc[N_MAX];
__device__ float  g_sdst[N_MAX];
__device__ int    g_cnt[N_MAX];
__device__ int    g_off[N_MAX];
__device__ int    g_cur[N_MAX];
__device__ int    g_cursor;
__device__ int2   g_rec[E_MAX];         // packed (src, ex-bits), dst-grouped
__device__ float4 g_Wfrag[8 * 8 * 32];  // W in mma-B fragment order: (b0hi,b1hi,b0lo,b1lo)

// ---------------------------------------------------------------------------
__device__ __forceinline__ float tf32_rna(float x) {
    float r;
    asm("cvt.rna.tf32.f32 %0, %1;" : "=f"(r) : "f"(x));
    return r;
}

__device__ __forceinline__ void mma_tf32(float d[4],
    uint32_t a0, uint32_t a1, uint32_t a2, uint32_t a3,
    uint32_t b0, uint32_t b1)
{
    asm volatile(
        "mma.sync.aligned.m16n8k8.row.col.f32.tf32.tf32.f32 "
        "{%0,%1,%2,%3}, {%4,%5,%6,%7}, {%8,%9}, {%0,%1,%2,%3};"
        : "+f"(d[0]), "+f"(d[1]), "+f"(d[2]), "+f"(d[3])
        : "r"(a0), "r"(a1), "r"(a2), "r"(a3), "r"(b0), "r"(b1));
}

// ---------------------------------------------------------------------------
// K0: zero counters + global cursor
// ---------------------------------------------------------------------------
__global__ void zero_kernel(int n_nodes) {
    int i = blockIdx.x * blockDim.x + threadIdx.x;
    if (i < n_nodes) g_cnt[i] = 0;
    if (i == 0) g_cursor = 0;
}

// ---------------------------------------------------------------------------
// K-W: pre-swizzle W into mma-B fragment order with tf32 hi/lo split.
// B tile (kt,nt): B[k][j] = W[j][k]. Thread lane (t=lane%4,q=lane/4) owns
// b0=B[t][q], b1=B[t+4][q]. Record = (b0hi, b1hi, b0lo, b1lo).
// ---------------------------------------------------------------------------
__global__ void __launch_bounds__(256) wsplit_kernel(const float* __restrict__ W) {
    int idx = blockIdx.x * 256 + threadIdx.x;
    if (idx >= 8 * 8 * 32) return;
    int lane = idx & 31, tile = idx >> 5;
    int kt = tile >> 3, nt = tile & 7;
    int t = lane & 3, q = lane >> 2;
    float w0 = W[(nt * 8 + q) * F + kt * 8 + t];
    float w1 = W[(nt * 8 + q) * F + kt * 8 + t + 4];
    float h0 = tf32_rna(w0), h1 = tf32_rna(w1);
    g_Wfrag[idx] = make_float4(h0, h1, tf32_rna(w0 - h0), tf32_rna(w1 - h1));
}

// ---------------------------------------------------------------------------
// K1: Wh = h @ W^T + Wb via 3xTF32 tensor-core mma; scores fused in epilogue.
// Block = 128 nodes, 8 warps; warp = 16 rows x 64 cols (8 n-tiles), k=64.
// ---------------------------------------------------------------------------
__global__ void __launch_bounds__(256) wh_tc_kernel(
    const float* __restrict__ h, const float* __restrict__ Wb,
    const float* __restrict__ a, int n_nodes)
{
    __shared__ __align__(16) float h_s[128 * 68];   // stride 68: conflict-free frag reads
    __shared__ float sWb[F];
    __shared__ float sa[2 * F];

    int tid = threadIdx.x;
    int m0 = blockIdx.x * 128;
    if (tid < F) sWb[tid] = Wb[tid];
    if (tid < 2 * F) sa[tid] = a[tid];

    // stage h rows (clamped) via float4
    for (int i4 = tid; i4 < 128 * 16; i4 += 256) {
        int r = i4 >> 4, c4 = i4 & 15;
        int n = min(m0 + r, n_nodes - 1);
        float4 v = __ldg(reinterpret_cast<const float4*>(&h[(size_t)n * F + c4 * 4]));
        *reinterpret_cast<float4*>(&h_s[r * 68 + c4 * 4]) = v;
    }
    __syncthreads();

    int warp = tid >> 5, lane = tid & 31;
    int t = lane & 3, q = lane >> 2;
    int mw = warp * 16;

    const float* shA  = &h_s[(mw + q) * 68];
    const float* shA8 = shA + 8 * 68;

    float d[8][4];
    #pragma unroll
    for (int nt = 0; nt < 8; nt++)
        d[nt][0] = d[nt][1] = d[nt][2] = d[nt][3] = 0.0f;

    #pragma unroll
    for (int kt = 0; kt < 8; kt++) {
        // A fragment (row-major): a0=(q,t) a1=(q+8,t) a2=(q,t+4) a3=(q+8,t+4)
        float a0f = shA [kt * 8 + t];
        float a1f = shA8[kt * 8 + t];
        float a2f = shA [kt * 8 + t + 4];
        float a3f = shA8[kt * 8 + t + 4];
        float h0 = tf32_rna(a0f), h1 = tf32_rna(a1f);
        float h2 = tf32_rna(a2f), h3 = tf32_rna(a3f);
        uint32_t ah0 = __float_as_uint(h0), ah1 = __float_as_uint(h1);
        uint32_t ah2 = __float_as_uint(h2), ah3 = __float_as_uint(h3);
        uint32_t al0 = __float_as_uint(tf32_rna(a0f - h0));
        uint32_t al1 = __float_as_uint(tf32_rna(a1f - h1));
        uint32_t al2 = __float_as_uint(tf32_rna(a2f - h2));
        uint32_t al3 = __float_as_uint(tf32_rna(a3f - h3));

        #pragma unroll
        for (int nt = 0; nt < 8; nt++) {
            float4 b = g_Wfrag[(kt * 8 + nt) * 32 + lane];   // coalesced, L1-hot
            uint32_t bh0 = __float_as_uint(b.x), bh1 = __float_as_uint(b.y);
            uint32_t bl0 = __float_as_uint(b.z), bl1 = __float_as_uint(b.w);
            mma_tf32(d[nt], ah0, ah1, ah2, ah3, bh0, bh1);   // hi*hi
            mma_tf32(d[nt], ah0, ah1, ah2, ah3, bl0, bl1);   // hi*lo
            mma_tf32(d[nt], al0, al1, al2, al3, bh0, bh1);   // lo*hi
        }
    }

    // Epilogue: bias, scores, store. D: c0=(q,2t) c1=(q,2t+1) c2/c3=(q+8,..)
    int row0 = m0 + mw + q;
    int row1 = row0 + 8;
    float p0 = 0.f, p1 = 0.f, q0 = 0.f, q1 = 0.f;
    #pragma unroll
    for (int nt = 0; nt < 8; nt++) {
        int c0 = nt * 8 + 2 * t, c1 = c0 + 1;
        float b0 = sWb[c0], b1 = sWb[c1];
        float v00 = d[nt][0] + b0, v01 = d[nt][1] + b1;   // row0
        float v10 = d[nt][2] + b0, v11 = d[nt][3] + b1;   // row1
        float s0 = sa[c0], s1 = sa[c1], t0 = sa[F + c0], t1 = sa[F + c1];
        p0 += v00 * s0 + v01 * s1;
        p1 += v10 * s0 + v11 * s1;
        q0 += v00 * t0 + v01 * t1;
        q1 += v10 * t0 + v11 * t1;
        if (row0 < n_nodes)
            *reinterpret_cast<float2*>(&g_Wh[(size_t)row0 * F + c0]) = make_float2(v00, v01);
        if (row1 < n_nodes)
            *reinterpret_cast<float2*>(&g_Wh[(size_t)row1 * F + c0]) = make_float2(v10, v11);
    }
    // reduce over the quad (t = 0..3)
    #pragma unroll
    for (int o = 1; o < 4; o <<= 1) {
        p0 += __shfl_xor_sync(0xffffffffu, p0, o);
        p1 += __shfl_xor_sync(0xffffffffu, p1, o);
        q0 += __shfl_xor_sync(0xffffffffu, q0, o);
        q1 += __shfl_xor_sync(0xffffffffu, q1, o);
    }
    if (t == 0) {
        if (row0 < n_nodes) { g_ssrc[row0] = p0; g_sdst[row0] = q0; }
        if (row1 < n_nodes) { g_ssrc[row1] = p1; g_sdst[row1] = q1; }
    }
}

// ---------------------------------------------------------------------------
// K2: count edges per dst
// ---------------------------------------------------------------------------
__global__ void __launch_bounds__(256) count_kernel(
    const int* __restrict__ dst, int n_edges)
{
    int i = blockIdx.x * blockDim.x + threadIdx.x;
    if (i < n_edges) atomicAdd(&g_cnt[dst[i]], 1);
}

// ---------------------------------------------------------------------------
// K3: CSR offsets (1024-thread block scan; ~98 cursor atomics)
// ---------------------------------------------------------------------------
__global__ void __launch_bounds__(1024) offset_kernel(int n_nodes) {
    __shared__ int warp_sums[32];
    __shared__ int block_base;

    int i = blockIdx.x * 1024 + threadIdx.x;
    int lane = threadIdx.x & 31;
    int wid  = threadIdx.x >> 5;
    int c = (i < n_nodes) ? g_cnt[i] : 0;

    int s = c;
    #pragma unroll
    for (int o = 1; o < 32; o <<= 1) {
        int t = __shfl_up_sync(0xffffffffu, s, o);
        if (lane >= o) s += t;
    }
    if (lane == 31) warp_sums[wid] = s;
    __syncthreads();

    if (wid == 0) {
        int v = warp_sums[lane];
        int sv = v;
        #pragma unroll
        for (int o = 1; o < 32; o <<= 1) {
            int t = __shfl_up_sync(0xffffffffu, sv, o);
            if (lane >= o) sv += t;
        }
        warp_sums[lane] = sv - v;
        if (lane == 31) block_base = atomicAdd(&g_cursor, sv);
    }
    __syncthreads();

    if (i < n_nodes) {
        int off = block_base + warp_sums[wid] + (s - c);
        g_off[i] = off;
        g_cur[i] = off;
    }
}

// ---------------------------------------------------------------------------
// K4: scatter — ex = exp(lrelu(...)); claim slot; write (src, ex).
// ---------------------------------------------------------------------------
__global__ void __launch_bounds__(256) scatter_kernel(
    const int* __restrict__ src, const int* __restrict__ dst,
    const float* __restrict__ ab_p, int n_edges)
{
    int i = blockIdx.x * blockDim.x + threadIdx.x;
    if (i >= n_edges) return;
    float ab = __ldg(ab_p);
    int s = src[i];
    int d = dst[i];
    float x = g_ssrc[s] + g_sdst[d] + ab;
    x = (x > 0.0f) ? x : ALPHA * x;
    float ex = expf(x);
    int pos = atomicAdd(&g_cur[d], 1);
    g_rec[pos] = make_int2(s, __float_as_int(ex));
}

// ---------------------------------------------------------------------------
// K5: gather — one warp per dst node, two edges per iter, float4 lanes.
// ---------------------------------------------------------------------------
__global__ void __launch_bounds__(256) gather_kernel(
    float* __restrict__ out, int n_nodes)
{
    int gwarp = (blockIdx.x * blockDim.x + threadIdx.x) >> 5;
    int lane = threadIdx.x & 31;
    if (gwarp >= n_nodes) return;

    int beg = g_off[gwarp];
    int cnt = g_cnt[gwarp];
    int half = lane >> 4;
    int l16  = lane & 15;

    const float4* wh4 = reinterpret_cast<const float4*>(g_Wh);
    float4 acc = make_float4(0.f, 0.f, 0.f, 0.f);
    float den = 0.0f;

    for (int base = 0; base < cnt; base += 32) {
        int idx = base + lane;
        int2 rec = (idx < cnt) ? __ldg(&g_rec[beg + idx]) : make_int2(0, 0);
        int m = min(cnt - base, 32);
        int iters = (m + 1) >> 1;
        #pragma unroll 4
        for (int k = 0; k < iters; k++) {
            int srcLane = 2 * k + half;
            int   s  = __shfl_sync(0xffffffffu, rec.x, srcLane);
            float ex = __int_as_float(__shfl_sync(0xffffffffu, rec.y, srcLane));
            float4 w = __ldg(&wh4[(size_t)s * 16 + l16]);
            acc.x = fmaf(ex, w.x, acc.x);
            acc.y = fmaf(ex, w.y, acc.y);
            acc.z = fmaf(ex, w.z, acc.z);
            acc.w = fmaf(ex, w.w, acc.w);
            den += ex;
        }
    }

    acc.x += __shfl_xor_sync(0xffffffffu, acc.x, 16);
    acc.y += __shfl_xor_sync(0xffffffffu, acc.y, 16);
    acc.z += __shfl_xor_sync(0xffffffffu, acc.z, 16);
    acc.w += __shfl_xor_sync(0xffffffffu, acc.w, 16);
    den   += __shfl_xor_sync(0xffffffffu, den,   16);

    if (half == 0) {
        float r = (den > 0.0f) ? (1.0f / den) : 1.0f;
        acc.x *= r; acc.y *= r; acc.z *= r; acc.w *= r;
        reinterpret_cast<float4*>(out)[(size_t)gwarp * 16 + l16] = acc;
    }
}

// ---------------------------------------------------------------------------
extern "C" void kernel_launch(void* const* d_in, const int* in_sizes, int n_in,
                              void* d_out, int out_size) {
    const float* h   = (const float*)d_in[0];
    const float* W   = (const float*)d_in[1];
    const float* Wb  = (const float*)d_in[2];
    const float* a   = (const float*)d_in[3];
    const float* ab  = (const float*)d_in[4];
    const int*   src = (const int*)d_in[5];
    const int*   dst = (const int*)d_in[6];
    float* out = (float*)d_out;

    int n_nodes = in_sizes[0] / F;
    int n_edges = in_sizes[5];

    static cudaStream_t side = nullptr;
    static cudaEvent_t evFork = nullptr, evJoin = nullptr;
    if (!side) {
        cudaStreamCreateWithFlags(&side, cudaStreamNonBlocking);
        cudaEventCreateWithFlags(&evFork, cudaEventDisableTiming);
        cudaEventCreateWithFlags(&evJoin, cudaEventDisableTiming);
    }

    // Fork: CSR prep (dst-only) runs beside W-split + tensor-core Wh.
    cudaEventRecord(evFork, 0);
    cudaStreamWaitEvent(side, evFork, 0);

    zero_kernel<<<(n_nodes + 255) / 256, 256, 0, side>>>(n_nodes);
    count_kernel<<<(n_edges + 255) / 256, 256, 0, side>>>(dst, n_edges);
    offset_kernel<<<(n_nodes + 1023) / 1024, 1024, 0, side>>>(n_nodes);
    cudaEventRecord(evJoin, side);

    wsplit_kernel<<<8, 256>>>(W);
    wh_tc_kernel<<<(n_nodes + 127) / 128, 256>>>(h, Wb, a, n_nodes);

    cudaStreamWaitEvent(0, evJoin, 0);
    scatter_kernel<<<(n_edges + 255) / 256, 256>>>(src, dst, ab, n_edges);
    gather_kernel<<<(n_nodes + 7) / 8, 256>>>(out, n_nodes);
}

// round 9
// speedup vs baseline: 1.2404x; 1.2404x over previous
#include <cuda_runtime.h>
#include <cuda_fp16.h>
#include <cstdint>

#define N_MAX 100000
#define E_MAX 1000000
#define F 64
#define ALPHA 0.2f
#define WPAD 68   // smem W row stride (floats): 272B rows -> 16B-aligned float4, conflict-free

// Scratch (static __device__ allocation — no cudaMalloc allowed)
// Permuted fp16 Wh: g_Whh[n*32 + l] = (Wh[n][l], Wh[n][l+32]). 12.8 MB, L2-resident.
__device__ __half2 g_Whh[N_MAX * 32];
__device__ float   g_ssrc[N_MAX];
__device__ float   g_sdst[N_MAX];
__device__ int     g_cnt[N_MAX];
__device__ int     g_off[N_MAX];
__device__ int     g_cur[N_MAX];
__device__ int     g_cursor;
__device__ int2    g_rec[E_MAX];        // packed (src, ex-bits), dst-grouped

// ---------------------------------------------------------------------------
// K0: zero counters + global cursor
// ---------------------------------------------------------------------------
__global__ void zero_kernel(int n_nodes) {
    int i = blockIdx.x * blockDim.x + threadIdx.x;
    if (i < n_nodes) g_cnt[i] = 0;
    if (i == 0) g_cursor = 0;
}

// ---------------------------------------------------------------------------
// K1: Wh = h @ W^T + Wb ; scores fused. R5-proven layout: 4 nodes/warp,
// lane owns cols (lane, lane+32); W rows via aligned conflict-free LDS.128
// (stride WPAD=68); h via broadcast LDS.128. Wh stored as permuted half2.
// ---------------------------------------------------------------------------
__global__ void __launch_bounds__(256) wh_kernel(
    const float* __restrict__ h, const float* __restrict__ W,
    const float* __restrict__ Wb, const float* __restrict__ a, int n_nodes)
{
    __shared__ float Wp[F * WPAD];          // Wp[j*WPAD + k] = W[j][k]
    __shared__ float sWb[F];
    __shared__ float sa[2 * F];
    __shared__ __align__(16) float hrow[8][4][F];   // [warp][node][k]

    int tid = threadIdx.x;
    for (int i = tid; i < F * F; i += 256) {
        int j = i >> 6, k = i & 63;
        Wp[j * WPAD + k] = W[i];
    }
    if (tid < F) sWb[tid] = Wb[tid];
    if (tid < 2 * F) sa[tid] = a[tid];

    int warp = tid >> 5;
    int lane = tid & 31;
    int n0 = (blockIdx.x * 8 + warp) * 4;

    #pragma unroll
    for (int i = 0; i < 4; i++) {
        int n = min(n0 + i, n_nodes - 1);
        hrow[warp][i][lane]      = h[(size_t)n * F + lane];
        hrow[warp][i][lane + 32] = h[(size_t)n * F + lane + 32];
    }
    __syncthreads();
    if (n0 >= n_nodes) return;

    const float4* w0p = reinterpret_cast<const float4*>(&Wp[lane * WPAD]);
    const float4* w1p = reinterpret_cast<const float4*>(&Wp[(lane + 32) * WPAD]);

    float acc0[4] = {0.f, 0.f, 0.f, 0.f};
    float acc1[4] = {0.f, 0.f, 0.f, 0.f};

    #pragma unroll
    for (int k4 = 0; k4 < 16; k4++) {
        float4 w0 = w0p[k4];                 // LDS.128, aligned, conflict-free
        float4 w1 = w1p[k4];
        #pragma unroll
        for (int i = 0; i < 4; i++) {
            float4 hv = reinterpret_cast<const float4*>(hrow[warp][i])[k4]; // broadcast
            acc0[i] = fmaf(hv.x, w0.x, acc0[i]);
            acc0[i] = fmaf(hv.y, w0.y, acc0[i]);
            acc0[i] = fmaf(hv.z, w0.z, acc0[i]);
            acc0[i] = fmaf(hv.w, w0.w, acc0[i]);
            acc1[i] = fmaf(hv.x, w1.x, acc1[i]);
            acc1[i] = fmaf(hv.y, w1.y, acc1[i]);
            acc1[i] = fmaf(hv.z, w1.z, acc1[i]);
            acc1[i] = fmaf(hv.w, w1.w, acc1[i]);
        }
    }

    float b0 = sWb[lane], b1 = sWb[lane + 32];
    float as0 = sa[lane], as1 = sa[lane + 32];
    float ad0 = sa[F + lane], ad1 = sa[F + lane + 32];

    #pragma unroll
    for (int i = 0; i < 4; i++) {
        int n = n0 + i;
        if (n >= n_nodes) break;
        float v0 = acc0[i] + b0;              // col lane
        float v1 = acc1[i] + b1;              // col lane+32
        g_Whh[(size_t)n * 32 + lane] = __floats2half2_rn(v0, v1);  // permuted pack

        float p = v0 * as0 + v1 * as1;
        float q = v0 * ad0 + v1 * ad1;
        #pragma unroll
        for (int o = 16; o > 0; o >>= 1) {
            p += __shfl_down_sync(0xffffffffu, p, o);
            q += __shfl_down_sync(0xffffffffu, q, o);
        }
        if (lane == 0) {
            g_ssrc[n] = p;
            g_sdst[n] = q;
        }
    }
}

// ---------------------------------------------------------------------------
// K2: count edges per dst
// ---------------------------------------------------------------------------
__global__ void __launch_bounds__(256) count_kernel(
    const int* __restrict__ dst, int n_edges)
{
    int i = blockIdx.x * blockDim.x + threadIdx.x;
    if (i < n_edges) atomicAdd(&g_cnt[dst[i]], 1);
}

// ---------------------------------------------------------------------------
// K3: CSR offsets (1024-thread block scan; ~98 cursor atomics)
// ---------------------------------------------------------------------------
__global__ void __launch_bounds__(1024) offset_kernel(int n_nodes) {
    __shared__ int warp_sums[32];
    __shared__ int block_base;

    int i = blockIdx.x * 1024 + threadIdx.x;
    int lane = threadIdx.x & 31;
    int wid  = threadIdx.x >> 5;
    int c = (i < n_nodes) ? g_cnt[i] : 0;

    int s = c;
    #pragma unroll
    for (int o = 1; o < 32; o <<= 1) {
        int t = __shfl_up_sync(0xffffffffu, s, o);
        if (lane >= o) s += t;
    }
    if (lane == 31) warp_sums[wid] = s;
    __syncthreads();

    if (wid == 0) {
        int v = warp_sums[lane];
        int sv = v;
        #pragma unroll
        for (int o = 1; o < 32; o <<= 1) {
            int t = __shfl_up_sync(0xffffffffu, sv, o);
            if (lane >= o) sv += t;
        }
        warp_sums[lane] = sv - v;
        if (lane == 31) block_base = atomicAdd(&g_cursor, sv);
    }
    __syncthreads();

    if (i < n_nodes) {
        int off = block_base + warp_sums[wid] + (s - c);
        g_off[i] = off;
        g_cur[i] = off;
    }
}

// ---------------------------------------------------------------------------
// K4: scatter — ex = exp(lrelu(s_src[src]+s_dst[dst]+ab)); claim slot;
// write packed (src, ex). Max-shift skipped (cancels exactly in attn).
// ---------------------------------------------------------------------------
__global__ void __launch_bounds__(256) scatter_kernel(
    const int* __restrict__ src, const int* __restrict__ dst,
    const float* __restrict__ ab_p, int n_edges)
{
    int i = blockIdx.x * blockDim.x + threadIdx.x;
    if (i >= n_edges) return;
    float ab = __ldg(ab_p);
    int s = src[i];
    int d = dst[i];
    float x = g_ssrc[s] + g_sdst[d] + ab;
    x = (x > 0.0f) ? x : ALPHA * x;
    float ex = expf(x);
    int pos = atomicAdd(&g_cur[d], 1);
    g_rec[pos] = make_int2(s, __float_as_int(ex));
}

// ---------------------------------------------------------------------------
// K5: gather — one warp per dst node, FOUR edges per iteration.
// Quarter-warp (8 lanes x 16B) covers a full fp16 row (128B).
// Permuted layout un-twists at the store into two coalesced float4 writes.
// ---------------------------------------------------------------------------
__global__ void __launch_bounds__(256) gather_kernel(
    float* __restrict__ out, int n_nodes)
{
    int gwarp = (blockIdx.x * blockDim.x + threadIdx.x) >> 5;
    int lane = threadIdx.x & 31;
    if (gwarp >= n_nodes) return;

    int beg = g_off[gwarp];
    int cnt = g_cnt[gwarp];
    int qtr = lane >> 3;            // which edge within the group of 4
    int l8  = lane & 7;             // 16B slot within the row

    const float4* whh4 = reinterpret_cast<const float4*>(g_Whh);
    // slot l8 holds half2 pairs for cols {4l8+j, 4l8+32+j}, j=0..3
    float acc[8] = {0.f, 0.f, 0.f, 0.f, 0.f, 0.f, 0.f, 0.f};
    float den = 0.0f;

    for (int base = 0; base < cnt; base += 32) {
        int idx = base + lane;
        int2 rec = (idx < cnt) ? __ldg(&g_rec[beg + idx]) : make_int2(0, 0);
        int m = min(cnt - base, 32);
        int iters = (m + 3) >> 2;
        #pragma unroll 4
        for (int k = 0; k < iters; k++) {
            int srcLane = 4 * k + qtr;           // >= m -> zeroed rec -> ex=0
            int   s  = __shfl_sync(0xffffffffu, rec.x, srcLane);
            float ex = __int_as_float(__shfl_sync(0xffffffffu, rec.y, srcLane));
            float4 w = __ldg(&whh4[(size_t)s * 8 + l8]);   // 4 half2
            float2 f0 = __half22float2(*reinterpret_cast<__half2*>(&w.x));
            float2 f1 = __half22float2(*reinterpret_cast<__half2*>(&w.y));
            float2 f2 = __half22float2(*reinterpret_cast<__half2*>(&w.z));
            float2 f3 = __half22float2(*reinterpret_cast<__half2*>(&w.w));
            acc[0] = fmaf(ex, f0.x, acc[0]);   // col 4l8+0
            acc[1] = fmaf(ex, f0.y, acc[1]);   // col 4l8+32
            acc[2] = fmaf(ex, f1.x, acc[2]);   // col 4l8+1
            acc[3] = fmaf(ex, f1.y, acc[3]);   // col 4l8+33
            acc[4] = fmaf(ex, f2.x, acc[4]);   // col 4l8+2
            acc[5] = fmaf(ex, f2.y, acc[5]);   // col 4l8+34
            acc[6] = fmaf(ex, f3.x, acc[6]);   // col 4l8+3
            acc[7] = fmaf(ex, f3.y, acc[7]);   // col 4l8+35
            den += ex;
        }
    }

    // combine the four quarters (same l8 slot across quarters)
    #pragma unroll
    for (int j = 0; j < 8; j++) {
        acc[j] += __shfl_xor_sync(0xffffffffu, acc[j], 8);
        acc[j] += __shfl_xor_sync(0xffffffffu, acc[j], 16);
    }
    den += __shfl_xor_sync(0xffffffffu, den, 8);
    den += __shfl_xor_sync(0xffffffffu, den, 16);

    if (qtr == 0) {
        float r = (den > 0.0f) ? (1.0f / den) : 1.0f;  // cnt==0 -> acc==0 == ref
        // cols 4l8..4l8+3 and 32+4l8..35+4l8: two coalesced float4 stores
        float4 lo = make_float4(acc[0] * r, acc[2] * r, acc[4] * r, acc[6] * r);
        float4 hi = make_float4(acc[1] * r, acc[3] * r, acc[5] * r, acc[7] * r);
        float4* op = reinterpret_cast<float4*>(out) + (size_t)gwarp * 16;
        op[l8]     = lo;
        op[l8 + 8] = hi;
    }
}

// ---------------------------------------------------------------------------
extern "C" void kernel_launch(void* const* d_in, const int* in_sizes, int n_in,
                              void* d_out, int out_size) {
    const float* h   = (const float*)d_in[0];
    const float* W   = (const float*)d_in[1];
    const float* Wb  = (const float*)d_in[2];
    const float* a   = (const float*)d_in[3];
    const float* ab  = (const float*)d_in[4];
    const int*   src = (const int*)d_in[5];
    const int*   dst = (const int*)d_in[6];
    float* out = (float*)d_out;

    int n_nodes = in_sizes[0] / F;
    int n_edges = in_sizes[5];

    static cudaStream_t side = nullptr;
    static cudaEvent_t evFork = nullptr, evJoin = nullptr;
    if (!side) {
        cudaStreamCreateWithFlags(&side, cudaStreamNonBlocking);
        cudaEventCreateWithFlags(&evFork, cudaEventDisableTiming);
        cudaEventCreateWithFlags(&evJoin, cudaEventDisableTiming);
    }

    // Fork: CSR prep (dst-only) runs beside wh (compute-bound).
    cudaEventRecord(evFork, 0);
    cudaStreamWaitEvent(side, evFork, 0);

    zero_kernel<<<(n_nodes + 255) / 256, 256, 0, side>>>(n_nodes);
    count_kernel<<<(n_edges + 255) / 256, 256, 0, side>>>(dst, n_edges);
    offset_kernel<<<(n_nodes + 1023) / 1024, 1024, 0, side>>>(n_nodes);
    cudaEventRecord(evJoin, side);

    wh_kernel<<<(n_nodes + 31) / 32, 256>>>(h, W, Wb, a, n_nodes);

    cudaStreamWaitEvent(0, evJoin, 0);
    scatter_kernel<<<(n_edges + 255) / 256, 256>>>(src, dst, ab, n_edges);
    gather_kernel<<<(n_nodes + 7) / 8, 256>>>(out, n_nodes);
}

// round 11
// speedup vs baseline: 1.3166x; 1.0614x over previous
#include <cuda_runtime.h>
#include <cuda_fp16.h>
#include <cstdint>

#define N_MAX 100000
#define E_MAX 1000000
#define F 64
#define ALPHA 0.2f
#define WPAD 68   // smem W row stride (floats): 272B rows -> 16B-aligned float4, conflict-free

typedef unsigned long long ull;

// Scratch (static __device__ allocation — no cudaMalloc allowed)
// Permuted fp16 Wh: g_Whh[n*32 + l] = (Wh[n][l], Wh[n][l+32]). 12.8 MB, L2-resident.
__device__ __half2 g_Whh[N_MAX * 32];
__device__ float   g_ssrc[N_MAX];
__device__ float   g_sdst[N_MAX];
__device__ int     g_cnt[N_MAX];
__device__ int     g_off[N_MAX];
__device__ int     g_cur[N_MAX];
__device__ int     g_cursor;
__device__ int2    g_rec[E_MAX];        // packed (src, ex-bits), dst-grouped

// ---- packed f32x2 helpers (Blackwell FFMA2) --------------------------------
__device__ __forceinline__ ull pack2(float lo, float hi) {
    ull r; asm("mov.b64 %0, {%1, %2};" : "=l"(r) : "f"(lo), "f"(hi)); return r;
}
__device__ __forceinline__ float2 unpack2(ull v) {
    float2 f; asm("mov.b64 {%0, %1}, %2;" : "=f"(f.x), "=f"(f.y) : "l"(v)); return f;
}
__device__ __forceinline__ ull ffma2(ull a, ull b, ull c) {
    ull d; asm("fma.rn.f32x2 %0, %1, %2, %3;" : "=l"(d) : "l"(a), "l"(b), "l"(c)); return d;
}

// ---------------------------------------------------------------------------
// K0: zero counters + global cursor
// ---------------------------------------------------------------------------
__global__ void zero_kernel(int n_nodes) {
    int i = blockIdx.x * blockDim.x + threadIdx.x;
    if (i < n_nodes) g_cnt[i] = 0;
    if (i == 0) g_cursor = 0;
}

// ---------------------------------------------------------------------------
// K1: Wh = h @ W^T + Wb ; scores fused. 8 nodes/warp as 4 node-PAIRS;
// accumulators are packed f32x2 (nodeA,nodeB), advanced with fma.rn.f32x2.
// h pre-interleaved in smem (512 B per pair: FIXED size [32][4]) so LDS.128
// yields 2 ready pairs; W splats packed once per k per warp.
// ---------------------------------------------------------------------------
__global__ void __launch_bounds__(256) wh_kernel(
    const float* __restrict__ h, const float* __restrict__ W,
    const float* __restrict__ Wb, const float* __restrict__ a, int n_nodes)
{
    __shared__ float Wp[F * WPAD];                       // Wp[j*WPAD+k] = W[j][k]
    __shared__ float sWb[F];
    __shared__ float sa[2 * F];
    // hp[warp][pair][k2][j]: j = (hA[2k2], hB[2k2], hA[2k2+1], hB[2k2+1]); 16 KB
    __shared__ __align__(16) float hp[8][4][32][4];

    int tid = threadIdx.x;
    for (int i = tid; i < F * F; i += 256) {
        int j = i >> 6, k = i & 63;
        Wp[j * WPAD + k] = W[i];
    }
    if (tid < F) sWb[tid] = Wb[tid];
    if (tid < 2 * F) sa[tid] = a[tid];

    int warp = tid >> 5;
    int lane = tid & 31;
    int n0 = (blockIdx.x * 8 + warp) * 8;

    // stage h interleaved: coalesced 128B global reads, scalar STS (one-time)
    #pragma unroll
    for (int j = 0; j < 16; j++) {
        int flat = j * 32 + lane;            // 0..511
        int nl = flat >> 6;                  // local node 0..7
        int k  = flat & 63;
        int n  = min(n0 + nl, n_nodes - 1);
        hp[warp][nl >> 1][k >> 1][(k & 1) * 2 + (nl & 1)] = h[(size_t)n * F + k];
    }
    __syncthreads();
    if (n0 >= n_nodes) return;

    const float4* w0p = reinterpret_cast<const float4*>(&Wp[lane * WPAD]);
    const float4* w1p = reinterpret_cast<const float4*>(&Wp[(lane + 32) * WPAD]);
    const ulonglong2* hp2[4];
    #pragma unroll
    for (int p = 0; p < 4; p++)
        hp2[p] = reinterpret_cast<const ulonglong2*>(&hp[warp][p][0][0]);

    ull acc0[4] = {0ull, 0ull, 0ull, 0ull};   // (nodeA,nodeB) col lane
    ull acc1[4] = {0ull, 0ull, 0ull, 0ull};   // (nodeA,nodeB) col lane+32

    #pragma unroll
    for (int k4 = 0; k4 < 16; k4++) {
        float4 w0 = w0p[k4];                 // W[lane][4k4..4k4+3]
        float4 w1 = w1p[k4];
        ull w0s0 = pack2(w0.x, w0.x), w0s1 = pack2(w0.y, w0.y);
        ull w0s2 = pack2(w0.z, w0.z), w0s3 = pack2(w0.w, w0.w);
        ull w1s0 = pack2(w1.x, w1.x), w1s1 = pack2(w1.y, w1.y);
        ull w1s2 = pack2(w1.z, w1.z), w1s3 = pack2(w1.w, w1.w);
        #pragma unroll
        for (int p = 0; p < 4; p++) {
            ulonglong2 ha = hp2[p][2 * k4];      // pairs for k=4k4, 4k4+1 (broadcast)
            ulonglong2 hb = hp2[p][2 * k4 + 1];  // pairs for k=4k4+2, 4k4+3
            acc0[p] = ffma2(ha.x, w0s0, acc0[p]);
            acc1[p] = ffma2(ha.x, w1s0, acc1[p]);
            acc0[p] = ffma2(ha.y, w0s1, acc0[p]);
            acc1[p] = ffma2(ha.y, w1s1, acc1[p]);
            acc0[p] = ffma2(hb.x, w0s2, acc0[p]);
            acc1[p] = ffma2(hb.x, w1s2, acc1[p]);
            acc0[p] = ffma2(hb.y, w0s3, acc0[p]);
            acc1[p] = ffma2(hb.y, w1s3, acc1[p]);
        }
    }

    float b0 = sWb[lane], b1 = sWb[lane + 32];
    float as0 = sa[lane], as1 = sa[lane + 32];
    float ad0 = sa[F + lane], ad1 = sa[F + lane + 32];

    #pragma unroll
    for (int p = 0; p < 4; p++) {
        float2 a0 = unpack2(acc0[p]);   // (nodeA, nodeB) col lane
        float2 a1 = unpack2(acc1[p]);   // (nodeA, nodeB) col lane+32
        #pragma unroll
        for (int w = 0; w < 2; w++) {
            int n = n0 + 2 * p + w;
            if (n >= n_nodes) break;
            float v0 = (w ? a0.y : a0.x) + b0;
            float v1 = (w ? a1.y : a1.x) + b1;
            g_Whh[(size_t)n * 32 + lane] = __floats2half2_rn(v0, v1);

            float pp = v0 * as0 + v1 * as1;
            float qq = v0 * ad0 + v1 * ad1;
            #pragma unroll
            for (int o = 16; o > 0; o >>= 1) {
                pp += __shfl_down_sync(0xffffffffu, pp, o);
                qq += __shfl_down_sync(0xffffffffu, qq, o);
            }
            if (lane == 0) {
                g_ssrc[n] = pp;
                g_sdst[n] = qq;
            }
        }
    }
}

// ---------------------------------------------------------------------------
// K2: count edges per dst
// ---------------------------------------------------------------------------
__global__ void __launch_bounds__(256) count_kernel(
    const int* __restrict__ dst, int n_edges)
{
    int i = blockIdx.x * blockDim.x + threadIdx.x;
    if (i < n_edges) atomicAdd(&g_cnt[dst[i]], 1);
}

// ---------------------------------------------------------------------------
// K3: CSR offsets (1024-thread block scan; ~98 cursor atomics)
// ---------------------------------------------------------------------------
__global__ void __launch_bounds__(1024) offset_kernel(int n_nodes) {
    __shared__ int warp_sums[32];
    __shared__ int block_base;

    int i = blockIdx.x * 1024 + threadIdx.x;
    int lane = threadIdx.x & 31;
    int wid  = threadIdx.x >> 5;
    int c = (i < n_nodes) ? g_cnt[i] : 0;

    int s = c;
    #pragma unroll
    for (int o = 1; o < 32; o <<= 1) {
        int t = __shfl_up_sync(0xffffffffu, s, o);
        if (lane >= o) s += t;
    }
    if (lane == 31) warp_sums[wid] = s;
    __syncthreads();

    if (wid == 0) {
        int v = warp_sums[lane];
        int sv = v;
        #pragma unroll
        for (int o = 1; o < 32; o <<= 1) {
            int t = __shfl_up_sync(0xffffffffu, sv, o);
            if (lane >= o) sv += t;
        }
        warp_sums[lane] = sv - v;
        if (lane == 31) block_base = atomicAdd(&g_cursor, sv);
    }
    __syncthreads();

    if (i < n_nodes) {
        int off = block_base + warp_sums[wid] + (s - c);
        g_off[i] = off;
        g_cur[i] = off;
    }
}

// ---------------------------------------------------------------------------
// K4: scatter — ex = exp(lrelu(s_src[src]+s_dst[dst]+ab)); claim slot;
// write packed (src, ex). Max-shift skipped (cancels exactly in attn).
// ---------------------------------------------------------------------------
__global__ void __launch_bounds__(256) scatter_kernel(
    const int* __restrict__ src, const int* __restrict__ dst,
    const float* __restrict__ ab_p, int n_edges)
{
    int i = blockIdx.x * blockDim.x + threadIdx.x;
    if (i >= n_edges) return;
    float ab = __ldg(ab_p);
    int s = src[i];
    int d = dst[i];
    float x = g_ssrc[s] + g_sdst[d] + ab;
    x = (x > 0.0f) ? x : ALPHA * x;
    float ex = expf(x);
    int pos = atomicAdd(&g_cur[d], 1);
    g_rec[pos] = make_int2(s, __float_as_int(ex));
}

// ---------------------------------------------------------------------------
// K5: gather — one warp per dst node, FOUR edges per iteration.
// Records staged via smem (conflict-free multicast LDS) instead of shfl.
// Quarter-warp (8 lanes x 16B) covers a full fp16 row (128B); permuted
// layout un-twists at the store into two coalesced float4 writes.
// ---------------------------------------------------------------------------
__global__ void __launch_bounds__(256) gather_kernel(
    float* __restrict__ out, int n_nodes)
{
    __shared__ int2 s_rec[8][32];

    int warp = threadIdx.x >> 5;
    int gwarp = (blockIdx.x * blockDim.x + threadIdx.x) >> 5;
    int lane = threadIdx.x & 31;
    if (gwarp >= n_nodes) return;

    int beg = g_off[gwarp];
    int cnt = g_cnt[gwarp];
    int qtr = lane >> 3;            // which edge within the group of 4
    int l8  = lane & 7;             // 16B slot within the row

    const float4* whh4 = reinterpret_cast<const float4*>(g_Whh);
    float acc[8] = {0.f, 0.f, 0.f, 0.f, 0.f, 0.f, 0.f, 0.f};
    float den = 0.0f;

    for (int base = 0; base < cnt; base += 32) {
        int idx = base + lane;
        s_rec[warp][lane] = (idx < cnt) ? __ldg(&g_rec[beg + idx]) : make_int2(0, 0);
        __syncwarp();
        int m = min(cnt - base, 32);
        int iters = (m + 3) >> 2;
        #pragma unroll 4
        for (int k = 0; k < iters; k++) {
            int2 rec = s_rec[warp][4 * k + qtr];   // multicast LDS.64
            int   s  = rec.x;
            float ex = __int_as_float(rec.y);
            float4 w = __ldg(&whh4[(size_t)s * 8 + l8]);   // 4 half2
            float2 f0 = __half22float2(*reinterpret_cast<__half2*>(&w.x));
            float2 f1 = __half22float2(*reinterpret_cast<__half2*>(&w.y));
            float2 f2 = __half22float2(*reinterpret_cast<__half2*>(&w.z));
            float2 f3 = __half22float2(*reinterpret_cast<__half2*>(&w.w));
            acc[0] = fmaf(ex, f0.x, acc[0]);   // col 4l8+0
            acc[1] = fmaf(ex, f0.y, acc[1]);   // col 4l8+32
            acc[2] = fmaf(ex, f1.x, acc[2]);   // col 4l8+1
            acc[3] = fmaf(ex, f1.y, acc[3]);   // col 4l8+33
            acc[4] = fmaf(ex, f2.x, acc[4]);   // col 4l8+2
            acc[5] = fmaf(ex, f2.y, acc[5]);   // col 4l8+34
            acc[6] = fmaf(ex, f3.x, acc[6]);   // col 4l8+3
            acc[7] = fmaf(ex, f3.y, acc[7]);   // col 4l8+35
            den += ex;
        }
        __syncwarp();
    }

    // combine the four quarters (same l8 slot across quarters)
    #pragma unroll
    for (int j = 0; j < 8; j++) {
        acc[j] += __shfl_xor_sync(0xffffffffu, acc[j], 8);
        acc[j] += __shfl_xor_sync(0xffffffffu, acc[j], 16);
    }
    den += __shfl_xor_sync(0xffffffffu, den, 8);
    den += __shfl_xor_sync(0xffffffffu, den, 16);

    if (qtr == 0) {
        float r = (den > 0.0f) ? (1.0f / den) : 1.0f;  // cnt==0 -> acc==0 == ref
        float4 lo = make_float4(acc[0] * r, acc[2] * r, acc[4] * r, acc[6] * r);
        float4 hi = make_float4(acc[1] * r, acc[3] * r, acc[5] * r, acc[7] * r);
        float4* op = reinterpret_cast<float4*>(out) + (size_t)gwarp * 16;
        op[l8]     = lo;
        op[l8 + 8] = hi;
    }
}

// ---------------------------------------------------------------------------
extern "C" void kernel_launch(void* const* d_in, const int* in_sizes, int n_in,
                              void* d_out, int out_size) {
    const float* h   = (const float*)d_in[0];
    const float* W   = (const float*)d_in[1];
    const float* Wb  = (const float*)d_in[2];
    const float* a   = (const float*)d_in[3];
    const float* ab  = (const float*)d_in[4];
    const int*   src = (const int*)d_in[5];
    const int*   dst = (const int*)d_in[6];
    float* out = (float*)d_out;

    int n_nodes = in_sizes[0] / F;
    int n_edges = in_sizes[5];

    static cudaStream_t side = nullptr;
    static cudaEvent_t evFork = nullptr, evJoin = nullptr;
    if (!side) {
        cudaStreamCreateWithFlags(&side, cudaStreamNonBlocking);
        cudaEventCreateWithFlags(&evFork, cudaEventDisableTiming);
        cudaEventCreateWithFlags(&evJoin, cudaEventDisableTiming);
    }

    // Fork: CSR prep (dst-only) runs beside wh (compute-bound).
    cudaEventRecord(evFork, 0);
    cudaStreamWaitEvent(side, evFork, 0);

    zero_kernel<<<(n_nodes + 255) / 256, 256, 0, side>>>(n_nodes);
    count_kernel<<<(n_edges + 255) / 256, 256, 0, side>>>(dst, n_edges);
    offset_kernel<<<(n_nodes + 1023) / 1024, 1024, 0, side>>>(n_nodes);
    cudaEventRecord(evJoin, side);

    wh_kernel<<<(n_nodes + 63) / 64, 256>>>(h, W, Wb, a, n_nodes);

    cudaStreamWaitEvent(0, evJoin, 0);
    scatter_kernel<<<(n_edges + 255) / 256, 256>>>(src, dst, ab, n_edges);
    gather_kernel<<<(n_nodes + 7) / 8, 256>>>(out, n_nodes);
}

// round 12
// speedup vs baseline: 1.3617x; 1.0342x over previous
#include <cuda_runtime.h>
#include <cuda_fp16.h>
#include <cstdint>

#define N_MAX 100000
#define E_MAX 1000000
#define F 64
#define ALPHA 0.2f
#define WPAD 68   // smem W row stride (floats): 272B rows -> 16B-aligned float4, conflict-free

typedef unsigned long long ull;

// Scratch (static __device__ allocation — no cudaMalloc allowed)
// Permuted fp16 Wh: g_Whh[n*32 + l] = (Wh[n][l], Wh[n][l+32]). 12.8 MB, L2-resident.
__device__ __half2 g_Whh[N_MAX * 32];
__device__ float   g_ssrc[N_MAX];
__device__ float   g_sdst[N_MAX];
__device__ int     g_cnt[N_MAX];
__device__ int     g_off[N_MAX];
__device__ int     g_cur[N_MAX];
__device__ int     g_cursor;
__device__ int     g_srcs[E_MAX];       // src indices, dst-grouped (4 MB)

// ---- packed f32x2 helpers (Blackwell FFMA2) --------------------------------
__device__ __forceinline__ ull pack2(float lo, float hi) {
    ull r; asm("mov.b64 %0, {%1, %2};" : "=l"(r) : "f"(lo), "f"(hi)); return r;
}
__device__ __forceinline__ float2 unpack2(ull v) {
    float2 f; asm("mov.b64 {%0, %1}, %2;" : "=f"(f.x), "=f"(f.y) : "l"(v)); return f;
}
__device__ __forceinline__ ull ffma2(ull a, ull b, ull c) {
    ull d; asm("fma.rn.f32x2 %0, %1, %2, %3;" : "=l"(d) : "l"(a), "l"(b), "l"(c)); return d;
}

// ---------------------------------------------------------------------------
// K0: zero counters + global cursor
// ---------------------------------------------------------------------------
__global__ void zero_kernel(int n_nodes) {
    int i = blockIdx.x * blockDim.x + threadIdx.x;
    if (i < n_nodes) g_cnt[i] = 0;
    if (i == 0) g_cursor = 0;
}

// ---------------------------------------------------------------------------
// K1: Wh = h @ W^T + Wb ; scores fused. 8 nodes/warp as 4 node-PAIRS;
// packed f32x2 accumulators via fma.rn.f32x2; h pre-interleaved in smem.
// ---------------------------------------------------------------------------
__global__ void __launch_bounds__(256) wh_kernel(
    const float* __restrict__ h, const float* __restrict__ W,
    const float* __restrict__ Wb, const float* __restrict__ a, int n_nodes)
{
    __shared__ float Wp[F * WPAD];                       // Wp[j*WPAD+k] = W[j][k]
    __shared__ float sWb[F];
    __shared__ float sa[2 * F];
    // hp[warp][pair][k2][j]: j = (hA[2k2], hB[2k2], hA[2k2+1], hB[2k2+1]); 16 KB
    __shared__ __align__(16) float hp[8][4][32][4];

    int tid = threadIdx.x;
    for (int i = tid; i < F * F; i += 256) {
        int j = i >> 6, k = i & 63;
        Wp[j * WPAD + k] = W[i];
    }
    if (tid < F) sWb[tid] = Wb[tid];
    if (tid < 2 * F) sa[tid] = a[tid];

    int warp = tid >> 5;
    int lane = tid & 31;
    int n0 = (blockIdx.x * 8 + warp) * 8;

    #pragma unroll
    for (int j = 0; j < 16; j++) {
        int flat = j * 32 + lane;            // 0..511
        int nl = flat >> 6;                  // local node 0..7
        int k  = flat & 63;
        int n  = min(n0 + nl, n_nodes - 1);
        hp[warp][nl >> 1][k >> 1][(k & 1) * 2 + (nl & 1)] = h[(size_t)n * F + k];
    }
    __syncthreads();
    if (n0 >= n_nodes) return;

    const float4* w0p = reinterpret_cast<const float4*>(&Wp[lane * WPAD]);
    const float4* w1p = reinterpret_cast<const float4*>(&Wp[(lane + 32) * WPAD]);
    const ulonglong2* hp2[4];
    #pragma unroll
    for (int p = 0; p < 4; p++)
        hp2[p] = reinterpret_cast<const ulonglong2*>(&hp[warp][p][0][0]);

    ull acc0[4] = {0ull, 0ull, 0ull, 0ull};   // (nodeA,nodeB) col lane
    ull acc1[4] = {0ull, 0ull, 0ull, 0ull};   // (nodeA,nodeB) col lane+32

    #pragma unroll
    for (int k4 = 0; k4 < 16; k4++) {
        float4 w0 = w0p[k4];
        float4 w1 = w1p[k4];
        ull w0s0 = pack2(w0.x, w0.x), w0s1 = pack2(w0.y, w0.y);
        ull w0s2 = pack2(w0.z, w0.z), w0s3 = pack2(w0.w, w0.w);
        ull w1s0 = pack2(w1.x, w1.x), w1s1 = pack2(w1.y, w1.y);
        ull w1s2 = pack2(w1.z, w1.z), w1s3 = pack2(w1.w, w1.w);
        #pragma unroll
        for (int p = 0; p < 4; p++) {
            ulonglong2 ha = hp2[p][2 * k4];
            ulonglong2 hb = hp2[p][2 * k4 + 1];
            acc0[p] = ffma2(ha.x, w0s0, acc0[p]);
            acc1[p] = ffma2(ha.x, w1s0, acc1[p]);
            acc0[p] = ffma2(ha.y, w0s1, acc0[p]);
            acc1[p] = ffma2(ha.y, w1s1, acc1[p]);
            acc0[p] = ffma2(hb.x, w0s2, acc0[p]);
            acc1[p] = ffma2(hb.x, w1s2, acc1[p]);
            acc0[p] = ffma2(hb.y, w0s3, acc0[p]);
            acc1[p] = ffma2(hb.y, w1s3, acc1[p]);
        }
    }

    float b0 = sWb[lane], b1 = sWb[lane + 32];
    float as0 = sa[lane], as1 = sa[lane + 32];
    float ad0 = sa[F + lane], ad1 = sa[F + lane + 32];

    #pragma unroll
    for (int p = 0; p < 4; p++) {
        float2 a0 = unpack2(acc0[p]);
        float2 a1 = unpack2(acc1[p]);
        #pragma unroll
        for (int w = 0; w < 2; w++) {
            int n = n0 + 2 * p + w;
            if (n >= n_nodes) break;
            float v0 = (w ? a0.y : a0.x) + b0;
            float v1 = (w ? a1.y : a1.x) + b1;
            g_Whh[(size_t)n * 32 + lane] = __floats2half2_rn(v0, v1);

            float pp = v0 * as0 + v1 * as1;
            float qq = v0 * ad0 + v1 * ad1;
            #pragma unroll
            for (int o = 16; o > 0; o >>= 1) {
                pp += __shfl_down_sync(0xffffffffu, pp, o);
                qq += __shfl_down_sync(0xffffffffu, qq, o);
            }
            if (lane == 0) {
                g_ssrc[n] = pp;
                g_sdst[n] = qq;
            }
        }
    }
}

// ---------------------------------------------------------------------------
// K2: count edges per dst
// ---------------------------------------------------------------------------
__global__ void __launch_bounds__(256) count_kernel(
    const int* __restrict__ dst, int n_edges)
{
    int i = blockIdx.x * blockDim.x + threadIdx.x;
    if (i < n_edges) atomicAdd(&g_cnt[dst[i]], 1);
}

// ---------------------------------------------------------------------------
// K3: CSR offsets (1024-thread block scan; ~98 cursor atomics)
// ---------------------------------------------------------------------------
__global__ void __launch_bounds__(1024) offset_kernel(int n_nodes) {
    __shared__ int warp_sums[32];
    __shared__ int block_base;

    int i = blockIdx.x * 1024 + threadIdx.x;
    int lane = threadIdx.x & 31;
    int wid  = threadIdx.x >> 5;
    int c = (i < n_nodes) ? g_cnt[i] : 0;

    int s = c;
    #pragma unroll
    for (int o = 1; o < 32; o <<= 1) {
        int t = __shfl_up_sync(0xffffffffu, s, o);
        if (lane >= o) s += t;
    }
    if (lane == 31) warp_sums[wid] = s;
    __syncthreads();

    if (wid == 0) {
        int v = warp_sums[lane];
        int sv = v;
        #pragma unroll
        for (int o = 1; o < 32; o <<= 1) {
            int t = __shfl_up_sync(0xffffffffu, sv, o);
            if (lane >= o) sv += t;
        }
        warp_sums[lane] = sv - v;
        if (lane == 31) block_base = atomicAdd(&g_cursor, sv);
    }
    __syncthreads();

    if (i < n_nodes) {
        int off = block_base + warp_sums[wid] + (s - c);
        g_off[i] = off;
        g_cur[i] = off;
    }
}

// ---------------------------------------------------------------------------
// K4: scatter — NO scores needed: just bucket src by dst. Runs on the side
// stream, fully hidden under wh. Slot order arbitrary; per-dst set fixed.
// ---------------------------------------------------------------------------
__global__ void __launch_bounds__(256) scatter_kernel(
    const int* __restrict__ src, const int* __restrict__ dst, int n_edges)
{
    int i = blockIdx.x * blockDim.x + threadIdx.x;
    if (i >= n_edges) return;
    int pos = atomicAdd(&g_cur[dst[i]], 1);
    g_srcs[pos] = src[i];
}

// ---------------------------------------------------------------------------
// K5: gather — one warp per dst node. Staging lanes compute ex inline
// (dst == gwarp, so sdst+ab is a warp constant; ssrc[s] is an L2-hot 4B load;
// exp once per edge). Inner loop: 4 edges/iter, quarter-warp rows, smem
// record multicast. Max-shift skipped (cancels exactly in attn).
// ---------------------------------------------------------------------------
__global__ void __launch_bounds__(256) gather_kernel(
    const float* __restrict__ ab_p, float* __restrict__ out, int n_nodes)
{
    __shared__ int2 s_rec[8][32];

    int warp = threadIdx.x >> 5;
    int gwarp = (blockIdx.x * blockDim.x + threadIdx.x) >> 5;
    int lane = threadIdx.x & 31;
    if (gwarp >= n_nodes) return;

    int beg = g_off[gwarp];
    int cnt = g_cnt[gwarp];
    int qtr = lane >> 3;            // which edge within the group of 4
    int l8  = lane & 7;             // 16B slot within the row

    float sdst_ab = g_sdst[gwarp] + __ldg(ab_p);   // warp-constant

    const float4* whh4 = reinterpret_cast<const float4*>(g_Whh);
    float acc[8] = {0.f, 0.f, 0.f, 0.f, 0.f, 0.f, 0.f, 0.f};
    float den = 0.0f;

    for (int base = 0; base < cnt; base += 32) {
        int idx = base + lane;
        int sld = 0;
        float ex = 0.0f;
        if (idx < cnt) {
            sld = __ldg(&g_srcs[beg + idx]);
            float x = __ldg(&g_ssrc[sld]) + sdst_ab;
            x = (x > 0.0f) ? x : ALPHA * x;
            ex = expf(x);
        }
        s_rec[warp][lane] = make_int2(sld, __float_as_int(ex));
        __syncwarp();
        int m = min(cnt - base, 32);
        int iters = (m + 3) >> 2;
        #pragma unroll 4
        for (int k = 0; k < iters; k++) {
            int2 rec = s_rec[warp][4 * k + qtr];   // multicast LDS.64
            int   s  = rec.x;
            float exk = __int_as_float(rec.y);
            float4 w = __ldg(&whh4[(size_t)s * 8 + l8]);   // 4 half2
            float2 f0 = __half22float2(*reinterpret_cast<__half2*>(&w.x));
            float2 f1 = __half22float2(*reinterpret_cast<__half2*>(&w.y));
            float2 f2 = __half22float2(*reinterpret_cast<__half2*>(&w.z));
            float2 f3 = __half22float2(*reinterpret_cast<__half2*>(&w.w));
            acc[0] = fmaf(exk, f0.x, acc[0]);   // col 4l8+0
            acc[1] = fmaf(exk, f0.y, acc[1]);   // col 4l8+32
            acc[2] = fmaf(exk, f1.x, acc[2]);   // col 4l8+1
            acc[3] = fmaf(exk, f1.y, acc[3]);   // col 4l8+33
            acc[4] = fmaf(exk, f2.x, acc[4]);   // col 4l8+2
            acc[5] = fmaf(exk, f2.y, acc[5]);   // col 4l8+34
            acc[6] = fmaf(exk, f3.x, acc[6]);   // col 4l8+3
            acc[7] = fmaf(exk, f3.y, acc[7]);   // col 4l8+35
            den += exk;
        }
        __syncwarp();
    }

    // combine the four quarters (same l8 slot across quarters)
    #pragma unroll
    for (int j = 0; j < 8; j++) {
        acc[j] += __shfl_xor_sync(0xffffffffu, acc[j], 8);
        acc[j] += __shfl_xor_sync(0xffffffffu, acc[j], 16);
    }
    den += __shfl_xor_sync(0xffffffffu, den, 8);
    den += __shfl_xor_sync(0xffffffffu, den, 16);

    if (qtr == 0) {
        float r = (den > 0.0f) ? (1.0f / den) : 1.0f;  // cnt==0 -> acc==0 == ref
        float4 lo = make_float4(acc[0] * r, acc[2] * r, acc[4] * r, acc[6] * r);
        float4 hi = make_float4(acc[1] * r, acc[3] * r, acc[5] * r, acc[7] * r);
        float4* op = reinterpret_cast<float4*>(out) + (size_t)gwarp * 16;
        op[l8]     = lo;
        op[l8 + 8] = hi;
    }
}

// ---------------------------------------------------------------------------
extern "C" void kernel_launch(void* const* d_in, const int* in_sizes, int n_in,
                              void* d_out, int out_size) {
    const float* h   = (const float*)d_in[0];
    const float* W   = (const float*)d_in[1];
    const float* Wb  = (const float*)d_in[2];
    const float* a   = (const float*)d_in[3];
    const float* ab  = (const float*)d_in[4];
    const int*   src = (const int*)d_in[5];
    const int*   dst = (const int*)d_in[6];
    float* out = (float*)d_out;

    int n_nodes = in_sizes[0] / F;
    int n_edges = in_sizes[5];

    static cudaStream_t side = nullptr;
    static cudaEvent_t evFork = nullptr, evJoin = nullptr;
    if (!side) {
        cudaStreamCreateWithFlags(&side, cudaStreamNonBlocking);
        cudaEventCreateWithFlags(&evFork, cudaEventDisableTiming);
        cudaEventCreateWithFlags(&evJoin, cudaEventDisableTiming);
    }

    // Side stream: full CSR build INCLUDING scatter (no score dependency)
    // — hidden under the wh GEMM on the main stream.
    cudaEventRecord(evFork, 0);
    cudaStreamWaitEvent(side, evFork, 0);

    zero_kernel<<<(n_nodes + 255) / 256, 256, 0, side>>>(n_nodes);
    count_kernel<<<(n_edges + 255) / 256, 256, 0, side>>>(dst, n_edges);
    offset_kernel<<<(n_nodes + 1023) / 1024, 1024, 0, side>>>(n_nodes);
    scatter_kernel<<<(n_edges + 255) / 256, 256, 0, side>>>(src, dst, n_edges);
    cudaEventRecord(evJoin, side);

    wh_kernel<<<(n_nodes + 63) / 64, 256>>>(h, W, Wb, a, n_nodes);

    // Gather needs wh (main) + CSR/scatter (side).
    cudaStreamWaitEvent(0, evJoin, 0);
    gather_kernel<<<(n_nodes + 7) / 8, 256>>>(ab, out, n_nodes);
}